// round 5
// baseline (speedup 1.0000x reference)
#include <cuda_runtime.h>
#include <cuda_fp16.h>
#include <cuda_bf16.h>

#define N_NODES 100000
#define N_EDGES 1600000
#define IN_F    128
#define HEADS   8
#define OUT_F   16
#define HD      128   // HEADS*OUT_F
#define NEG_SLOPE 0.2f

// ---------------- scratch (device globals; no allocation allowed) ------------
__device__ __align__(16) float  g_h  [N_NODES * HD];   // fp32 projected features (residual)
__device__ __align__(16) __half g_hh [N_NODES * HD];   // fp16 copy for edge gathers
__device__ __align__(16) float  g_el [N_NODES * HEADS];
__device__ __align__(16) float  g_er [N_NODES * HEADS];
__device__ __align__(16) int    g_deg   [N_NODES];
__device__ __align__(16) int    g_off   [N_NODES + 4];
__device__ __align__(16) int    g_cursor[N_NODES];
__device__ __align__(16) int    g_csr_src[N_EDGES];

// ---------------- K1: h = feats @ W, el/er (fp32 FFMA, validated R3 loop) ----
#define K1_BLOCK 512
#define K1_WARPS (K1_BLOCK / 32)
#define K1_SMEM  (128*128*4 + K1_WARPS*4*128*4 + 2*128*4)   // 99328 B

__global__ void __launch_bounds__(K1_BLOCK, 2)
k_proj(const float* __restrict__ feats, const float* __restrict__ W,
       const float* __restrict__ attn_l, const float* __restrict__ attn_r)
{
    extern __shared__ float smem[];
    float* Ws   = smem;                      // 128*128
    float* frow = Ws + 128 * 128;            // K1_WARPS*4*128
    float* al   = frow + K1_WARPS * 4 * 128; // 128
    float* ar   = al + 128;                  // 128

    const int tid = threadIdx.x;

    for (int i = tid; i < 128 * 128 / 4; i += K1_BLOCK)
        ((float4*)Ws)[i] = ((const float4*)W)[i];
    if (tid < 128) { al[tid] = attn_l[tid]; ar[tid] = attn_r[tid]; }
    __syncthreads();

    const int warp = tid >> 5, lane = tid & 31;
    const int gw = blockIdx.x * K1_WARPS + warp;
    const int nw = gridDim.x * K1_WARPS;
    float* fr = frow + warp * 4 * 128;
    const int head  = lane >> 2;
    const int cbase = lane * 4;
    const float4* Ws4 = (const float4*)Ws;

    for (int base = gw * 4; base < N_NODES; base += nw * 4) {
        #pragma unroll
        for (int r = 0; r < 4; r++)
            ((float4*)(fr + r * 128))[lane] = ((const float4*)(feats + (base + r) * IN_F))[lane];
        __syncwarp();

        float4 a0 = {0,0,0,0}, a1 = {0,0,0,0}, a2 = {0,0,0,0}, a3 = {0,0,0,0};
        #pragma unroll 2
        for (int k4 = 0; k4 < 128; k4 += 4) {
            float4 F0 = *(const float4*)(fr + k4);
            float4 F1 = *(const float4*)(fr + 128 + k4);
            float4 F2 = *(const float4*)(fr + 256 + k4);
            float4 F3 = *(const float4*)(fr + 384 + k4);
            float f0[4] = {F0.x, F0.y, F0.z, F0.w};
            float f1[4] = {F1.x, F1.y, F1.z, F1.w};
            float f2[4] = {F2.x, F2.y, F2.z, F2.w};
            float f3[4] = {F3.x, F3.y, F3.z, F3.w};
            #pragma unroll
            for (int kk = 0; kk < 4; kk++) {
                float4 w = Ws4[(k4 + kk) * 32 + lane];
                a0.x += f0[kk]*w.x; a0.y += f0[kk]*w.y; a0.z += f0[kk]*w.z; a0.w += f0[kk]*w.w;
                a1.x += f1[kk]*w.x; a1.y += f1[kk]*w.y; a1.z += f1[kk]*w.z; a1.w += f1[kk]*w.w;
                a2.x += f2[kk]*w.x; a2.y += f2[kk]*w.y; a2.z += f2[kk]*w.z; a2.w += f2[kk]*w.w;
                a3.x += f3[kk]*w.x; a3.y += f3[kk]*w.y; a3.z += f3[kk]*w.z; a3.w += f3[kk]*w.w;
            }
        }

        float4 accs[4] = {a0, a1, a2, a3};
        #pragma unroll
        for (int r = 0; r < 4; r++) {
            float4 a = accs[r];
            int row = base + r;
            float pl = a.x * al[cbase] + a.y * al[cbase+1] + a.z * al[cbase+2] + a.w * al[cbase+3];
            float pr = a.x * ar[cbase] + a.y * ar[cbase+1] + a.z * ar[cbase+2] + a.w * ar[cbase+3];
            pl += __shfl_xor_sync(0xffffffffu, pl, 1);
            pl += __shfl_xor_sync(0xffffffffu, pl, 2);
            pr += __shfl_xor_sync(0xffffffffu, pr, 1);
            pr += __shfl_xor_sync(0xffffffffu, pr, 2);
            if ((lane & 3) == 0) {
                g_el[row * HEADS + head] = pl;
                g_er[row * HEADS + head] = pr;
            }
            ((float4*)(g_h + row * HD))[lane] = a;
            __half2 p01 = __floats2half2_rn(a.x, a.y);
            __half2 p23 = __floats2half2_rn(a.z, a.w);
            uint2 hu;
            *reinterpret_cast<__half2*>(&hu.x) = p01;
            *reinterpret_cast<__half2*>(&hu.y) = p23;
            ((uint2*)(g_hh + row * HD))[lane] = hu;
        }
        __syncwarp();
    }
}

// ---------------- CSR build (validated R4) ------------------------------------
__global__ void __launch_bounds__(512)
k_zero()
{
    for (int i = blockIdx.x * 512 + threadIdx.x; i < N_NODES; i += gridDim.x * 512)
        g_deg[i] = 0;
}

__global__ void __launch_bounds__(256)
k_hist(const int* __restrict__ dst)
{
    int i = blockIdx.x * 256 + threadIdx.x;          // 4 edges per thread
    if (i * 4 >= N_EDGES) return;
    int4 d4 = ((const int4*)dst)[i];
    atomicAdd(&g_deg[d4.x], 1);
    atomicAdd(&g_deg[d4.y], 1);
    atomicAdd(&g_deg[d4.z], 1);
    atomicAdd(&g_deg[d4.w], 1);
}

__global__ void __launch_bounds__(1024)
k_scan()
{
    __shared__ int wsum[32];
    __shared__ int carry_s;
    const int tid = threadIdx.x, lane = tid & 31, warp = tid >> 5;
    if (tid == 0) carry_s = 0;
    __syncthreads();

    const int4* deg4 = (const int4*)g_deg;
    for (int base = 0; base < N_NODES; base += 4096) {
        int i0 = base + tid * 4;
        int4 v = (i0 < N_NODES) ? deg4[i0 >> 2] : make_int4(0, 0, 0, 0);
        int t = v.x + v.y + v.z + v.w;
        int x = t;
        #pragma unroll
        for (int o = 1; o < 32; o <<= 1) {
            int y = __shfl_up_sync(0xffffffffu, x, o);
            if (lane >= o) x += y;
        }
        if (lane == 31) wsum[warp] = x;
        __syncthreads();
        if (warp == 0) {
            int s = wsum[lane];
            #pragma unroll
            for (int o = 1; o < 32; o <<= 1) {
                int y = __shfl_up_sync(0xffffffffu, s, o);
                if (lane >= o) s += y;
            }
            wsum[lane] = s;
        }
        __syncthreads();
        int warpoff = (warp == 0) ? 0 : wsum[warp - 1];
        int excl = carry_s + warpoff + x - t;
        if (i0 < N_NODES) {
            int4 o;
            o.x = excl;
            o.y = o.x + v.x;
            o.z = o.y + v.y;
            o.w = o.z + v.z;
            ((int4*)g_off)[i0 >> 2] = o;
            ((int4*)g_cursor)[i0 >> 2] = o;
        }
        int blocktotal = wsum[31];
        __syncthreads();
        if (tid == 0) carry_s += blocktotal;
        __syncthreads();
    }
    if (tid == 0) g_off[N_NODES] = carry_s;
}

__global__ void __launch_bounds__(256)
k_scatter(const int* __restrict__ src, const int* __restrict__ dst)
{
    int i = blockIdx.x * 256 + threadIdx.x;          // 4 edges per thread
    if (i * 4 >= N_EDGES) return;
    int4 s4 = ((const int4*)src)[i];
    int4 d4 = ((const int4*)dst)[i];
    int p0 = atomicAdd(&g_cursor[d4.x], 1);
    int p1 = atomicAdd(&g_cursor[d4.y], 1);
    int p2 = atomicAdd(&g_cursor[d4.z], 1);
    int p3 = atomicAdd(&g_cursor[d4.w], 1);
    g_csr_src[p0] = s4.x;
    g_csr_src[p1] = s4.y;
    g_csr_src[p2] = s4.z;
    g_csr_src[p3] = s4.w;
}

// ---------------- K3: warp per dst node, two-phase (lane-per-edge exp) -------
// Phase 1: each lane computes exp(leaky(el[s]+er[d])) for ALL 8 heads of one
//          edge, stages into padded smem [head*33 + edge] (conflict-free).
// Phase 2: per edge: 1 shfl (src idx) + 1 LDS (this lane's head exp, broadcast
//          across quad) + fp16 uint2 gather + 4 FMA. sum accumulates
//          identically in all 4 lanes of each head-quad.
__global__ void __launch_bounds__(256)
k_agg(const float* __restrict__ bias, float* __restrict__ out)
{
    __shared__ float s_ex[8][8 * 33];   // [warp][head*33 + edge]
    const int warp = threadIdx.x >> 5, lane = threadIdx.x & 31;
    const int d = (blockIdx.x * 256 + threadIdx.x) >> 5;
    if (d >= N_NODES) return;
    float* ex_w = &s_ex[warp][0];

    const int start = g_off[d], end = g_off[d + 1];

    // er[d][0..7] broadcast into registers (all lanes same address)
    float4 er0 = ((const float4*)(g_er + d * HEADS))[0];
    float4 er1 = ((const float4*)(g_er + d * HEADS))[1];
    float er_[8] = {er0.x, er0.y, er0.z, er0.w, er1.x, er1.y, er1.z, er1.w};

    float sum = 0.f;
    float4 acc = {0.f, 0.f, 0.f, 0.f};
    const int hoff = (lane >> 2) * 33;   // this lane's head row in smem

    for (int base = start; base < end; base += 32) {
        const int idx = base + lane;
        const bool valid = idx < end;
        const int myS = valid ? g_csr_src[idx] : 0;
        const int cnt = min(32, end - base);

        // ---- phase 1: lane-per-edge exponentials ----
        if (valid) {
            float4 e0 = ((const float4*)(g_el + myS * HEADS))[0];
            float4 e1 = ((const float4*)(g_el + myS * HEADS))[1];
            float ev[8] = {e0.x, e0.y, e0.z, e0.w, e1.x, e1.y, e1.z, e1.w};
            #pragma unroll
            for (int j = 0; j < 8; j++) {
                float a = ev[j] + er_[j];
                a = fmaxf(a, 0.f) + NEG_SLOPE * fminf(a, 0.f);
                ex_w[j * 33 + lane] = __expf(a);
            }
        }
        __syncwarp();

        // ---- phase 2: accumulate ----
        #pragma unroll 4
        for (int t = 0; t < cnt; t++) {
            int s = __shfl_sync(0xffffffffu, myS, t);
            float exv = ex_w[hoff + t];
            sum += exv;
            uint2 hv = ((const uint2*)(g_hh + s * HD))[lane];
            __half2 h01 = *reinterpret_cast<__half2*>(&hv.x);
            __half2 h23 = *reinterpret_cast<__half2*>(&hv.y);
            float2 f01 = __half22float2(h01);
            float2 f23 = __half22float2(h23);
            acc.x += exv * f01.x; acc.y += exv * f01.y;
            acc.z += exv * f23.x; acc.w += exv * f23.y;
        }
        __syncwarp();
    }

    float inv = (end > start) ? 1.f / sum : 0.f;   // zero in-degree guard
    float4 hd = ((const float4*)(g_h + d * HD))[lane];   // fp32 residual
    float4 b  = ((const float4*)bias)[lane];
    float4 o;
    o.x = acc.x * inv + hd.x + b.x;
    o.y = acc.y * inv + hd.y + b.y;
    o.z = acc.z * inv + hd.z + b.z;
    o.w = acc.w * inv + hd.w + b.w;
    ((float4*)(out + d * HD))[lane] = o;
}

// ---------------- launch ------------------------------------------------------
extern "C" void kernel_launch(void* const* d_in, const int* in_sizes, int n_in,
                              void* d_out, int out_size)
{
    const float* feats  = (const float*)d_in[0];
    const float* W      = (const float*)d_in[1];
    const float* attn_l = (const float*)d_in[2];
    const float* attn_r = (const float*)d_in[3];
    const float* bias   = (const float*)d_in[4];
    const int*   src    = (const int*)d_in[5];
    const int*   dst    = (const int*)d_in[6];
    float* out = (float*)d_out;

    cudaFuncSetAttribute(k_proj, cudaFuncAttributeMaxDynamicSharedMemorySize, K1_SMEM);

    cudaStream_t side;
    cudaEvent_t ev_fork, ev_join;
    cudaStreamCreateWithFlags(&side, cudaStreamNonBlocking);
    cudaEventCreateWithFlags(&ev_fork, cudaEventDisableTiming);
    cudaEventCreateWithFlags(&ev_join, cudaEventDisableTiming);

    cudaEventRecord(ev_fork, 0);
    cudaStreamWaitEvent(side, ev_fork, 0);

    // CSR build chain on side stream (independent of projection)
    k_zero<<<64, 512, 0, side>>>();
    k_hist<<<(N_EDGES / 4 + 255) / 256, 256, 0, side>>>(dst);
    k_scan<<<1, 1024, 0, side>>>();
    k_scatter<<<(N_EDGES / 4 + 255) / 256, 256, 0, side>>>(src, dst);
    cudaEventRecord(ev_join, side);

    // projection on the main (captured) stream, concurrent with CSR build
    k_proj<<<296, K1_BLOCK, K1_SMEM>>>(feats, W, attn_l, attn_r);

    cudaStreamWaitEvent(0, ev_join, 0);
    k_agg<<<(N_NODES * 32 + 255) / 256, 256>>>(bias, out);
}

// round 6
// speedup vs baseline: 1.1223x; 1.1223x over previous
#include <cuda_runtime.h>
#include <cuda_fp16.h>
#include <cuda_bf16.h>

#define N_NODES 100000
#define N_EDGES 1600000
#define IN_F    128
#define HEADS   8
#define OUT_F   16
#define HD      128   // HEADS*OUT_F
#define NEG_SLOPE 0.2f

// ---------------- scratch (device globals; no allocation allowed) ------------
__device__ __align__(16) float  g_h  [N_NODES * HD];   // fp32 projected features
__device__ __align__(16) float  g_el [N_NODES * HEADS];
__device__ __align__(16) float  g_er [N_NODES * HEADS];
__device__ __align__(16) int    g_deg   [N_NODES];
__device__ __align__(16) int    g_off   [N_NODES + 4];
__device__ __align__(16) int    g_cursor[N_NODES];
__device__ __align__(16) int    g_csr_src[N_EDGES];
__device__ int g_bsum[32];
__device__ int g_boff[32];

// ---------------- K1: h = feats @ W, el/er  (8 rows per warp) ----------------
#define K1_BLOCK 256
#define K1_WARPS (K1_BLOCK / 32)                              // 8
#define K1_ROWS  8
#define K1_SMEM  (128*128*4 + K1_WARPS*K1_ROWS*128*4 + 2*128*4)  // 99328 B

__global__ void __launch_bounds__(K1_BLOCK, 2)
k_proj(const float* __restrict__ feats, const float* __restrict__ W,
       const float* __restrict__ attn_l, const float* __restrict__ attn_r)
{
    extern __shared__ float smem[];
    float* Ws   = smem;                              // 128*128
    float* frow = Ws + 128 * 128;                    // 8 warps * 8 rows * 128
    float* al   = frow + K1_WARPS * K1_ROWS * 128;   // 128
    float* ar   = al + 128;                          // 128

    const int tid = threadIdx.x;

    for (int i = tid; i < 128 * 128 / 4; i += K1_BLOCK)
        ((float4*)Ws)[i] = ((const float4*)W)[i];
    if (tid < 128) { al[tid] = attn_l[tid]; ar[tid] = attn_r[tid]; }
    __syncthreads();

    const int warp = tid >> 5, lane = tid & 31;
    const int gw = blockIdx.x * K1_WARPS + warp;
    const int nw = gridDim.x * K1_WARPS;
    float* fr = frow + warp * K1_ROWS * 128;
    const int head  = lane >> 2;
    const int cbase = lane * 4;
    const float4* Ws4 = (const float4*)Ws;

    for (int base = gw * K1_ROWS; base < N_NODES; base += nw * K1_ROWS) {
        #pragma unroll
        for (int r = 0; r < K1_ROWS; r++)
            ((float4*)(fr + r * 128))[lane] = ((const float4*)(feats + (base + r) * IN_F))[lane];
        __syncwarp();

        float4 acc[K1_ROWS];
        #pragma unroll
        for (int r = 0; r < K1_ROWS; r++) acc[r] = make_float4(0.f, 0.f, 0.f, 0.f);

        for (int k4 = 0; k4 < 128; k4 += 4) {
            float f[K1_ROWS][4];
            #pragma unroll
            for (int r = 0; r < K1_ROWS; r++) {
                float4 F = *(const float4*)(fr + r * 128 + k4);
                f[r][0] = F.x; f[r][1] = F.y; f[r][2] = F.z; f[r][3] = F.w;
            }
            #pragma unroll
            for (int kk = 0; kk < 4; kk++) {
                float4 w = Ws4[(k4 + kk) * 32 + lane];
                #pragma unroll
                for (int r = 0; r < K1_ROWS; r++) {
                    acc[r].x += f[r][kk] * w.x;
                    acc[r].y += f[r][kk] * w.y;
                    acc[r].z += f[r][kk] * w.z;
                    acc[r].w += f[r][kk] * w.w;
                }
            }
        }

        #pragma unroll
        for (int r = 0; r < K1_ROWS; r++) {
            float4 a = acc[r];
            int row = base + r;
            float pl = a.x * al[cbase] + a.y * al[cbase+1] + a.z * al[cbase+2] + a.w * al[cbase+3];
            float pr = a.x * ar[cbase] + a.y * ar[cbase+1] + a.z * ar[cbase+2] + a.w * ar[cbase+3];
            pl += __shfl_xor_sync(0xffffffffu, pl, 1);
            pl += __shfl_xor_sync(0xffffffffu, pl, 2);
            pr += __shfl_xor_sync(0xffffffffu, pr, 1);
            pr += __shfl_xor_sync(0xffffffffu, pr, 2);
            if ((lane & 3) == 0) {
                g_el[row * HEADS + head] = pl;
                g_er[row * HEADS + head] = pr;
            }
            ((float4*)(g_h + row * HD))[lane] = a;
        }
        __syncwarp();
    }
}

// ---------------- CSR build ---------------------------------------------------
__global__ void __launch_bounds__(512)
k_zero()
{
    for (int i = blockIdx.x * 512 + threadIdx.x; i < N_NODES; i += gridDim.x * 512)
        g_deg[i] = 0;
}

__global__ void __launch_bounds__(256)
k_hist(const int* __restrict__ dst)
{
    int i = blockIdx.x * 256 + threadIdx.x;          // 4 edges per thread
    if (i * 4 >= N_EDGES) return;
    int4 d4 = ((const int4*)dst)[i];
    atomicAdd(&g_deg[d4.x], 1);
    atomicAdd(&g_deg[d4.y], 1);
    atomicAdd(&g_deg[d4.z], 1);
    atomicAdd(&g_deg[d4.w], 1);
}

// ---- parallel scan: 25 blocks of 4096 elems, then block-sum scan, then add --
#define SCAN_BLOCKS ((N_NODES + 4095) / 4096)   // 25

__global__ void __launch_bounds__(1024)
k_scan1()
{
    __shared__ int wsum[32];
    const int tid = threadIdx.x, lane = tid & 31, warp = tid >> 5;
    const int i0 = blockIdx.x * 4096 + tid * 4;

    int4 v = (i0 < N_NODES) ? ((const int4*)g_deg)[i0 >> 2] : make_int4(0, 0, 0, 0);
    int t = v.x + v.y + v.z + v.w;
    int x = t;
    #pragma unroll
    for (int o = 1; o < 32; o <<= 1) {
        int y = __shfl_up_sync(0xffffffffu, x, o);
        if (lane >= o) x += y;
    }
    if (lane == 31) wsum[warp] = x;
    __syncthreads();
    if (warp == 0) {
        int s = wsum[lane];
        #pragma unroll
        for (int o = 1; o < 32; o <<= 1) {
            int y = __shfl_up_sync(0xffffffffu, s, o);
            if (lane >= o) s += y;
        }
        wsum[lane] = s;
    }
    __syncthreads();
    int warpoff = (warp == 0) ? 0 : wsum[warp - 1];
    int excl = warpoff + x - t;             // block-local exclusive prefix
    if (i0 < N_NODES) {
        int4 o;
        o.x = excl;
        o.y = o.x + v.x;
        o.z = o.y + v.y;
        o.w = o.z + v.z;
        ((int4*)g_off)[i0 >> 2] = o;
    }
    if (tid == 0) g_bsum[blockIdx.x] = wsum[31];
}

__global__ void __launch_bounds__(32)
k_scan2()
{
    int lane = threadIdx.x;
    int v = (lane < SCAN_BLOCKS) ? g_bsum[lane] : 0;
    int x = v;
    #pragma unroll
    for (int o = 1; o < 32; o <<= 1) {
        int y = __shfl_up_sync(0xffffffffu, x, o);
        if (lane >= o) x += y;
    }
    if (lane < SCAN_BLOCKS) g_boff[lane] = x - v;   // exclusive
}

__global__ void __launch_bounds__(1024)
k_scan3()
{
    const int i0 = blockIdx.x * 4096 + threadIdx.x * 4;
    if (i0 < N_NODES) {
        int boff = g_boff[blockIdx.x];
        int4 o = ((const int4*)g_off)[i0 >> 2];
        o.x += boff; o.y += boff; o.z += boff; o.w += boff;
        ((int4*)g_off)[i0 >> 2] = o;
        ((int4*)g_cursor)[i0 >> 2] = o;
    }
    if (blockIdx.x == 0 && threadIdx.x == 0) g_off[N_NODES] = N_EDGES;
}

__global__ void __launch_bounds__(256)
k_scatter(const int* __restrict__ src, const int* __restrict__ dst)
{
    int i = blockIdx.x * 256 + threadIdx.x;          // 4 edges per thread
    if (i * 4 >= N_EDGES) return;
    int4 s4 = ((const int4*)src)[i];
    int4 d4 = ((const int4*)dst)[i];
    int p0 = atomicAdd(&g_cursor[d4.x], 1);
    int p1 = atomicAdd(&g_cursor[d4.y], 1);
    int p2 = atomicAdd(&g_cursor[d4.z], 1);
    int p3 = atomicAdd(&g_cursor[d4.w], 1);
    g_csr_src[p0] = s4.x;
    g_csr_src[p1] = s4.y;
    g_csr_src[p2] = s4.z;
    g_csr_src[p3] = s4.w;
}

// ---------------- K3: warp per dst node (exact R3 best-known loop) -----------
__global__ void __launch_bounds__(256)
k_agg(const float* __restrict__ bias, float* __restrict__ out)
{
    int gw = (blockIdx.x * 256 + threadIdx.x) >> 5;
    int lane = threadIdx.x & 31;
    if (gw >= N_NODES) return;
    const int d = gw;
    const int head = lane >> 2;

    int start = g_off[d], end = g_off[d + 1];
    float erd = (lane < 8) ? g_er[d * HEADS + lane] : 0.f;
    float sum = 0.f;
    float4 acc = {0.f, 0.f, 0.f, 0.f};

    for (int base = start; base < end; base += 32) {
        int idx = base + lane;
        int myS = (idx < end) ? g_csr_src[idx] : 0;
        int cnt = min(32, end - base);
        #pragma unroll 4
        for (int t = 0; t < cnt; t++) {
            int s = __shfl_sync(0xffffffffu, myS, t);
            float ex = 0.f;
            if (lane < 8) {
                float a = g_el[s * HEADS + lane] + erd;
                a = a > 0.f ? a : NEG_SLOPE * a;
                ex = __expf(a);
                sum += ex;
            }
            float exh = __shfl_sync(0xffffffffu, ex, head);
            float4 hv = ((const float4*)(g_h + s * HD))[lane];
            acc.x += exh * hv.x; acc.y += exh * hv.y;
            acc.z += exh * hv.z; acc.w += exh * hv.w;
        }
    }

    float sumh = __shfl_sync(0xffffffffu, sum, head);
    float inv = (end > start) ? 1.f / sumh : 0.f;   // zero in-degree guard
    float4 hd = ((const float4*)(g_h + d * HD))[lane];
    float4 b  = ((const float4*)bias)[lane];
    float4 o;
    o.x = acc.x * inv + hd.x + b.x;
    o.y = acc.y * inv + hd.y + b.y;
    o.z = acc.z * inv + hd.z + b.z;
    o.w = acc.w * inv + hd.w + b.w;
    ((float4*)(out + d * HD))[lane] = o;
}

// ---------------- launch ------------------------------------------------------
extern "C" void kernel_launch(void* const* d_in, const int* in_sizes, int n_in,
                              void* d_out, int out_size)
{
    const float* feats  = (const float*)d_in[0];
    const float* W      = (const float*)d_in[1];
    const float* attn_l = (const float*)d_in[2];
    const float* attn_r = (const float*)d_in[3];
    const float* bias   = (const float*)d_in[4];
    const int*   src    = (const int*)d_in[5];
    const int*   dst    = (const int*)d_in[6];
    float* out = (float*)d_out;

    cudaFuncSetAttribute(k_proj, cudaFuncAttributeMaxDynamicSharedMemorySize, K1_SMEM);

    cudaStream_t side;
    cudaEvent_t ev_fork, ev_join;
    cudaStreamCreateWithFlags(&side, cudaStreamNonBlocking);
    cudaEventCreateWithFlags(&ev_fork, cudaEventDisableTiming);
    cudaEventCreateWithFlags(&ev_join, cudaEventDisableTiming);

    cudaEventRecord(ev_fork, 0);
    cudaStreamWaitEvent(side, ev_fork, 0);

    // CSR build chain on side stream (independent of projection)
    k_zero<<<64, 512, 0, side>>>();
    k_hist<<<(N_EDGES / 4 + 255) / 256, 256, 0, side>>>(dst);
    k_scan1<<<SCAN_BLOCKS, 1024, 0, side>>>();
    k_scan2<<<1, 32, 0, side>>>();
    k_scan3<<<SCAN_BLOCKS, 1024, 0, side>>>();
    k_scatter<<<(N_EDGES / 4 + 255) / 256, 256, 0, side>>>(src, dst);
    cudaEventRecord(ev_join, side);

    // projection on the main (captured) stream, concurrent with CSR build
    k_proj<<<296, K1_BLOCK, K1_SMEM>>>(feats, W, attn_l, attn_r);

    cudaStreamWaitEvent(0, ev_join, 0);
    k_agg<<<(N_NODES * 32 + 255) / 256, 256>>>(bias, out);
}